// round 3
// baseline (speedup 1.0000x reference)
#include <cuda_runtime.h>

#define BB 8
#define CC 128
#define NN 4096
#define DD 16

// ---------------- scratch (static __device__, allocation-free) ----------------
__device__ float g_q [BB * NN * DD];          // [b][n][d]   2 MB
__device__ float g_k [BB * DD * NN];          // [b][d][n]   2 MB
__device__ float g_vT[BB * NN * CC];          // [b][n][c]  16 MB

// =============================================================================
// K1: projections  q = wq@x, k = wk@x, vT = (wv@x)^T   (per-token channel dots)
// grid: B * (N/128) = 256 blocks, 256 threads
// smem: xs[128][128] + wvT[128][128] + wqT[128][16] + wkT[128][16] = 144 KB
// =============================================================================
__global__ void __launch_bounds__(256) proj_kernel(
    const float* __restrict__ x,  const float* __restrict__ wq,
    const float* __restrict__ wk, const float* __restrict__ wv)
{
    extern __shared__ float sm[];
    float* xs  = sm;                    // [c][n] 128x128
    float* wvs = xs  + 128 * 128;       // [c][cout]
    float* wqs = wvs + 128 * 128;       // [c][d]
    float* wks = wqs + 128 * 16;        // [c][d]

    const int tid = threadIdx.x;
    const int b   = blockIdx.x >> 5;
    const int n0  = (blockIdx.x & 31) << 7;

    for (int i = tid; i < 128 * 128; i += 256) {
        int co = i >> 7, c = i & 127;
        wvs[c * 128 + co] = wv[i];                 // transpose wv -> [c][cout]
    }
    for (int i = tid; i < 16 * 128; i += 256) {
        int d = i >> 7, c = i & 127;
        wqs[c * 16 + d] = wq[i];
        wks[c * 16 + d] = wk[i];
    }
    const float* xb = x + (size_t)b * CC * NN + n0;
    for (int i = tid; i < 128 * 128; i += 256) {
        int c = i >> 7, n = i & 127;
        xs[i] = xb[(size_t)c * NN + n];
    }
    __syncthreads();

    const int n    = tid & 127;
    const int half = tid >> 7;            // 0/1 : split channels between 2 threads/token

    float aq[8], ak[8], av[64];
#pragma unroll
    for (int j = 0; j < 8; j++) { aq[j] = 0.f; ak[j] = 0.f; }
#pragma unroll
    for (int j = 0; j < 64; j++) av[j] = 0.f;

    for (int c = 0; c < 128; c++) {
        float xv = xs[c * 128 + n];
        const float* wr = wvs + c * 128 + half * 64;
#pragma unroll
        for (int j = 0; j < 64; j++) av[j] += wr[j] * xv;
        const float* qr = wqs + c * 16 + half * 8;
        const float* kr = wks + c * 16 + half * 8;
#pragma unroll
        for (int j = 0; j < 8; j++) { aq[j] += qr[j] * xv; ak[j] += kr[j] * xv; }
    }

    const int nn_ = n0 + n;
    float* qo = g_q + ((size_t)b * NN + nn_) * DD + half * 8;
#pragma unroll
    for (int j = 0; j < 8; j++) qo[j] = aq[j];
#pragma unroll
    for (int j = 0; j < 8; j++)
        g_k[(size_t)b * DD * NN + (size_t)(half * 8 + j) * NN + nn_] = ak[j];
    float* vo = g_vT + ((size_t)b * NN + nn_) * CC + half * 64;
#pragma unroll
    for (int j = 0; j < 64; j++) vo[j] = av[j];
}

// =============================================================================
// K2: energy (fp32) + softmax + write normalized attention rows
// grid: B * (N/8) = 4096 blocks, 256 threads
// smem: e[8][4096] (128KB) + ktile[16][128] + q[8][16]
// =============================================================================
__global__ void __launch_bounds__(256) attn_kernel(float* __restrict__ att)
{
    extern __shared__ float sm[];
    float* e  = sm;                 // [8][NN]
    float* kt = e + 8 * NN;         // [16][128]
    float* qs = kt + 16 * 128;      // [8][16]

    const int tid = threadIdx.x;
    const int b   = blockIdx.x >> 9;
    const int i0  = (blockIdx.x & 511) << 3;

    if (tid < 128)
        qs[tid] = g_q[((size_t)b * NN + i0) * DD + tid];   // 8 rows x 16 contiguous
    __syncthreads();

    const float* kb = g_k + (size_t)b * DD * NN;
    const int m  = tid & 127;
    const int rg = (tid >> 7) * 4;

    for (int mt = 0; mt < 32; mt++) {
        const int m0 = mt << 7;
        for (int i = tid; i < 16 * 128; i += 256) {
            int d = i >> 7, mm = i & 127;
            kt[i] = kb[(size_t)d * NN + m0 + mm];
        }
        __syncthreads();

        float a0 = 0.f, a1 = 0.f, a2 = 0.f, a3 = 0.f;
#pragma unroll
        for (int d = 0; d < 16; d++) {
            float kv = kt[d * 128 + m];
            a0 += qs[(rg + 0) * 16 + d] * kv;
            a1 += qs[(rg + 1) * 16 + d] * kv;
            a2 += qs[(rg + 2) * 16 + d] * kv;
            a3 += qs[(rg + 3) * 16 + d] * kv;
        }
        e[(rg + 0) * NN + m0 + m] = a0;
        e[(rg + 1) * NN + m0 + m] = a1;
        e[(rg + 2) * NN + m0 + m] = a2;
        e[(rg + 3) * NN + m0 + m] = a3;
        __syncthreads();
    }

    // softmax: one warp per row
    const int w = tid >> 5, lane = tid & 31;
    float* er = e + w * NN;

    float mx = -3.0e38f;
    for (int j = lane; j < NN; j += 32) mx = fmaxf(mx, er[j]);
#pragma unroll
    for (int o = 16; o > 0; o >>= 1) mx = fmaxf(mx, __shfl_xor_sync(0xffffffffu, mx, o));

    float s = 0.f;
    for (int j = lane; j < NN; j += 32) { float v = __expf(er[j] - mx); er[j] = v; s += v; }
#pragma unroll
    for (int o = 16; o > 0; o >>= 1) s += __shfl_xor_sync(0xffffffffu, s, o);
    const float inv = 1.0f / s;

    float* arow = att + ((size_t)b * NN + i0 + w) * NN;
    for (int j = lane; j < NN; j += 32) arow[j] = er[j] * inv;
}

// =============================================================================
// K3: out^T = Att x vT  (tf32 tensor-core GEMM), fused epilogue gamma*out + x
// per batch: [4096 x 128] = [4096 x 4096] x [4096 x 128]
// block tile 64(i) x 128(c), K-tile 32, double-buffered smem
// grid: B * (N/64) = 512 blocks, 256 threads (8 warps: 2(M) x 4(N))
// =============================================================================
#define AS_STRIDE 36
#define BS_STRIDE 136
#define AS_SZ (64 * AS_STRIDE)
#define BS_SZ (32 * BS_STRIDE)

__device__ __forceinline__ unsigned f2tf(float f) {
    unsigned u; asm("cvt.rna.tf32.f32 %0, %1;" : "=r"(u) : "f"(f)); return u;
}

__global__ void __launch_bounds__(256) pv_kernel(
    const float* __restrict__ att, const float* __restrict__ x,
    const float* __restrict__ gamma_p, float* __restrict__ out)
{
    extern __shared__ float sm[];
    float* Asm[2] = { sm, sm + AS_SZ };
    float* Bsm[2] = { sm + 2 * AS_SZ, sm + 2 * AS_SZ + BS_SZ };

    const int tid  = threadIdx.x;
    const int b    = blockIdx.x >> 6;
    const int i0   = (blockIdx.x & 63) << 6;
    const int lane = tid & 31;
    const int w    = tid >> 5, wm = w >> 2, wn = w & 3;

    const float* attb = att  + (size_t)b * NN * NN;
    const float* vtb  = g_vT + (size_t)b * NN * CC;

    // load index helpers: A tile 64x32 (2 float4/thr), B tile 32x128 (4 float4/thr)
    const int arow = tid >> 2;                 // 0..63
    const int aj0  = (tid & 3) * 2;            // float4 slot base (0..6)
    const int bj   = tid >> 5;                 // 0..7 (row within tile, +8*q)
    const int bc4  = tid & 31;                 // float4 col

    float4 aP[2], bP[4];
#pragma unroll
    for (int s = 0; s < 2; s++)
        aP[s] = *(const float4*)(attb + (size_t)(i0 + arow) * NN + (aj0 + s) * 4);
#pragma unroll
    for (int q = 0; q < 4; q++)
        bP[q] = *(const float4*)(vtb + (size_t)(bj + 8 * q) * CC + bc4 * 4);

#define STS_TILE(buf)                                                          \
    do {                                                                       \
        _Pragma("unroll")                                                      \
        for (int s = 0; s < 2; s++) {                                          \
            float4 v = aP[s];                                                  \
            float4 t = make_float4(__uint_as_float(f2tf(v.x)),                 \
                                   __uint_as_float(f2tf(v.y)),                 \
                                   __uint_as_float(f2tf(v.z)),                 \
                                   __uint_as_float(f2tf(v.w)));                \
            *(float4*)&Asm[buf][arow * AS_STRIDE + (aj0 + s) * 4] = t;         \
        }                                                                      \
        _Pragma("unroll")                                                      \
        for (int q = 0; q < 4; q++) {                                          \
            float4 v = bP[q];                                                  \
            float4 t = make_float4(__uint_as_float(f2tf(v.x)),                 \
                                   __uint_as_float(f2tf(v.y)),                 \
                                   __uint_as_float(f2tf(v.z)),                 \
                                   __uint_as_float(f2tf(v.w)));                \
            *(float4*)&Bsm[buf][(bj + 8 * q) * BS_STRIDE + bc4 * 4] = t;       \
        }                                                                      \
    } while (0)

    STS_TILE(0);
    __syncthreads();

    float acc[2][4][4];
#pragma unroll
    for (int fm = 0; fm < 2; fm++)
#pragma unroll
        for (int fn = 0; fn < 4; fn++)
#pragma unroll
            for (int r = 0; r < 4; r++) acc[fm][fn][r] = 0.f;

    for (int kt = 0; kt < 128; kt++) {
        const int cur = kt & 1;
        if (kt < 127) {
            const int j0 = (kt + 1) << 5;
#pragma unroll
            for (int s = 0; s < 2; s++)
                aP[s] = *(const float4*)(attb + (size_t)(i0 + arow) * NN + j0 + (aj0 + s) * 4);
#pragma unroll
            for (int q = 0; q < 4; q++)
                bP[q] = *(const float4*)(vtb + (size_t)(j0 + bj + 8 * q) * CC + bc4 * 4);
        }
        const float* Ac = Asm[cur];
        const float* Bc = Bsm[cur];

#pragma unroll
        for (int kk = 0; kk < 4; kk++) {
            unsigned af[2][4], bf[4][2];
#pragma unroll
            for (int fm = 0; fm < 2; fm++) {
                int r = wm * 32 + fm * 16 + (lane >> 2);
                int c = kk * 8 + (lane & 3);
                af[fm][0] = __float_as_uint(Ac[r * AS_STRIDE + c]);
                af[fm][1] = __float_as_uint(Ac[(r + 8) * AS_STRIDE + c]);
                af[fm][2] = __float_as_uint(Ac[r * AS_STRIDE + c + 4]);
                af[fm][3] = __float_as_uint(Ac[(r + 8) * AS_STRIDE + c + 4]);
            }
#pragma unroll
            for (int fn = 0; fn < 4; fn++) {
                int kb = kk * 8 + (lane & 3);
                int cb = wn * 32 + fn * 8 + (lane >> 2);
                bf[fn][0] = __float_as_uint(Bc[kb * BS_STRIDE + cb]);
                bf[fn][1] = __float_as_uint(Bc[(kb + 4) * BS_STRIDE + cb]);
            }
#pragma unroll
            for (int fm = 0; fm < 2; fm++)
#pragma unroll
                for (int fn = 0; fn < 4; fn++)
                    asm volatile(
                        "mma.sync.aligned.m16n8k8.row.col.f32.tf32.tf32.f32 "
                        "{%0,%1,%2,%3}, {%4,%5,%6,%7}, {%8,%9}, {%0,%1,%2,%3};\n"
                        : "+f"(acc[fm][fn][0]), "+f"(acc[fm][fn][1]),
                          "+f"(acc[fm][fn][2]), "+f"(acc[fm][fn][3])
                        : "r"(af[fm][0]), "r"(af[fm][1]), "r"(af[fm][2]), "r"(af[fm][3]),
                          "r"(bf[fn][0]), "r"(bf[fn][1]));
        }

        if (kt < 127) STS_TILE(cur ^ 1);
        __syncthreads();
    }

    // epilogue: stage out^T tile [64 i][128 c] in smem, write gamma*out + x
    float* os = sm;   // [64][129]
#pragma unroll
    for (int fm = 0; fm < 2; fm++)
#pragma unroll
        for (int fn = 0; fn < 4; fn++) {
            int r = wm * 32 + fm * 16 + (lane >> 2);
            int c = wn * 32 + fn * 8 + 2 * (lane & 3);
            os[r * 129 + c]           = acc[fm][fn][0];
            os[r * 129 + c + 1]       = acc[fm][fn][1];
            os[(r + 8) * 129 + c]     = acc[fm][fn][2];
            os[(r + 8) * 129 + c + 1] = acc[fm][fn][3];
        }
    __syncthreads();

    const float gma = gamma_p[0];
    const int cq = tid >> 6;     // 0..3
    const int il = tid & 63;
    for (int cc = 0; cc < 128; cc += 4) {
        int c = cc + cq;
        float v = os[il * 129 + c];
        size_t gi = ((size_t)b * CC + c) * NN + i0 + il;
        out[gi] = gma * v + x[gi];
    }
}

// =============================================================================
// launch
// =============================================================================
extern "C" void kernel_launch(void* const* d_in, const int* in_sizes, int n_in,
                              void* d_out, int out_size)
{
    (void)in_sizes; (void)n_in;
    const float* x  = (const float*)d_in[0];
    const float* wq = (const float*)d_in[1];
    const float* wk = (const float*)d_in[2];
    const float* wv = (const float*)d_in[3];
    const float* gm = (const float*)d_in[4];
    float* out = (float*)d_out;

    const size_t att_elems = (size_t)BB * NN * NN;          // 134217728
    size_t att_off = ((size_t)out_size > att_elems) ? ((size_t)out_size - att_elems) : 0;
    float* att = out + att_off;                              // attention region of d_out

    const int PROJ_SMEM = (128 * 128 * 2 + 128 * 16 * 2) * 4;          // 147456
    const int ATT_SMEM  = (8 * NN + 16 * 128 + 128) * 4;               // 139776
    const int PV_SMEM   = (2 * AS_SZ + 2 * BS_SZ) * 4;                 // 53248

    cudaFuncSetAttribute(proj_kernel, cudaFuncAttributeMaxDynamicSharedMemorySize, PROJ_SMEM);
    cudaFuncSetAttribute(attn_kernel, cudaFuncAttributeMaxDynamicSharedMemorySize, ATT_SMEM);
    cudaFuncSetAttribute(pv_kernel,   cudaFuncAttributeMaxDynamicSharedMemorySize, PV_SMEM);

    proj_kernel<<<256,  256, PROJ_SMEM>>>(x, wq, wk, wv);
    attn_kernel<<<4096, 256, ATT_SMEM>>>(att);
    pv_kernel  <<<512,  256, PV_SMEM>>>(att, x, gm, out);
}